// round 4
// baseline (speedup 1.0000x reference)
#include <cuda_runtime.h>
#include <cstddef>
#include <cstdint>

// Problem constants
#define BB    4096      // batch
#define LAT   256
#define HH    512
#define AA    64
#define LL    128
#define NSTEP 127       // L-1 sequential GRU steps
#define KCAT  576       // H + A
#define NCAT  1536      // 3H

// -------------------- scratch (__device__ globals, no allocs) --------------------
__device__ __align__(256) float g_hx  [BB * KCAT];                 // [h | x] current step input
__device__ __align__(256) float g_tmp1[BB * HH];
__device__ __align__(256) float g_tmp2[BB * HH];
__device__ __align__(256) float g_O   [BB * NCAT];                 // step GEMM output (r,z pre-act + hn)
__device__ __align__(256) float g_hall[(size_t)NSTEP * BB * HH];   // all hidden states (1.06 GB)
__device__ __align__(256) float g_p1  [(size_t)NSTEP * BB * HH];   // pred intermediate 1
__device__ __align__(256) float g_p2  [(size_t)NSTEP * BB * AA];   // pred intermediate 2
__device__ __align__(256) float g_wcat[NCAT * KCAT];               // [W_hh | W_ih] (zeros in x-part of hn cols)
__device__ __align__(256) float g_bcat[NCAT];

// -------------------- generic fp32 tiled GEMM --------------------
// C[m,n] = act( sum_k A[m,k] * Bw[n,k] + bias[n] )
// A row-major (lda), Bw row-major [N,K] (torch weight layout).
// Requirements: M % 128 == 0, K % 16 == 0. N arbitrary (guarded).
// act: 0 = none, 1 = tanh.  scatter: 0 = C[m*ldc+n], 1 = out[b,s+1,n] with m = s*BB+b.
#define GBM 128
#define GBN 128
#define GBK 16

__global__ __launch_bounds__(256, 2)
void gemm_kernel(const float* __restrict__ A, int lda,
                 const float* __restrict__ Bw,
                 const float* __restrict__ bias,
                 float* __restrict__ C, int ldc,
                 int M, int N, int K, int act, int scatter)
{
    __shared__ float As[GBK][GBM + 4];
    __shared__ float Bs[GBK][GBN + 4];

    const int tid = threadIdx.x;
    const int tx = tid & 15;        // 0..15  (N dir)
    const int ty = tid >> 4;        // 0..15  (M dir)
    const int row0 = blockIdx.y * GBM;
    const int col0 = blockIdx.x * GBN;

    float acc[8][8];
#pragma unroll
    for (int i = 0; i < 8; i++)
#pragma unroll
        for (int j = 0; j < 8; j++) acc[i][j] = 0.f;

    for (int k0 = 0; k0 < K; k0 += GBK) {
        // Load A tile: 128x16 floats = 512 float4, 2 per thread
#pragma unroll
        for (int i = 0; i < 2; i++) {
            int li = tid * 2 + i;          // 0..511
            int r  = li >> 2;              // 0..127
            int c4 = (li & 3) * 4;         // 0,4,8,12
            float4 v = *(const float4*)(A + (size_t)(row0 + r) * lda + k0 + c4);
            As[c4 + 0][r] = v.x; As[c4 + 1][r] = v.y;
            As[c4 + 2][r] = v.z; As[c4 + 3][r] = v.w;
        }
        // Load B tile (guard n < N)
#pragma unroll
        for (int i = 0; i < 2; i++) {
            int li = tid * 2 + i;
            int n  = li >> 2;
            int c4 = (li & 3) * 4;
            float4 v = make_float4(0.f, 0.f, 0.f, 0.f);
            if (col0 + n < N)
                v = *(const float4*)(Bw + (size_t)(col0 + n) * K + k0 + c4);
            Bs[c4 + 0][n] = v.x; Bs[c4 + 1][n] = v.y;
            Bs[c4 + 2][n] = v.z; Bs[c4 + 3][n] = v.w;
        }
        __syncthreads();

#pragma unroll
        for (int kk = 0; kk < GBK; kk++) {
            float4 a0 = *(const float4*)&As[kk][ty * 8];
            float4 a1 = *(const float4*)&As[kk][ty * 8 + 4];
            float4 b0 = *(const float4*)&Bs[kk][tx * 8];
            float4 b1 = *(const float4*)&Bs[kk][tx * 8 + 4];
            float av[8] = {a0.x, a0.y, a0.z, a0.w, a1.x, a1.y, a1.z, a1.w};
            float bv[8] = {b0.x, b0.y, b0.z, b0.w, b1.x, b1.y, b1.z, b1.w};
#pragma unroll
            for (int i = 0; i < 8; i++)
#pragma unroll
                for (int j = 0; j < 8; j++)
                    acc[i][j] += av[i] * bv[j];
        }
        __syncthreads();
    }

    // Epilogue
#pragma unroll
    for (int i = 0; i < 8; i++) {
        int m = row0 + ty * 8 + i;
#pragma unroll
        for (int j = 0; j < 8; j++) {
            int n = col0 + tx * 8 + j;
            if (n < N) {
                float v = acc[i][j] + bias[n];
                if (act == 1) v = tanhf(v);
                size_t idx;
                if (scatter) {
                    int b = m & (BB - 1);
                    int s = m >> 12;                   // m / 4096
                    idx = (size_t)b * (LL * AA) + (size_t)(s + 1) * AA + n;
                } else {
                    idx = (size_t)m * ldc + n;
                }
                C[idx] = v;
            }
        }
    }
}

// -------------------- GRU gate fusion kernel --------------------
// Per step s: reads O (r/z pre-act incl. both biases, hn incl. b_hh_n),
// computes inn = b_ih_n + x . W_ih_n  (K=64 dot, smem-tiled),
// n = tanh(inn + r*hn), h_new = (1-z)*n + z*h_prev.
// Writes h_new into g_hall[s] and g_hx (h part); j-tile 0 also stages x_{s+1}.
__global__ __launch_bounds__(256)
void gates_kernel(const float* __restrict__ O,
                  const float* __restrict__ target,   // [4096,128,64]
                  const float* __restrict__ W_ih,     // [1536,64]
                  const float* __restrict__ b_ih,     // [1536]
                  float* __restrict__ hall_s,         // g_hall + s*BB*HH
                  int s)
{
    __shared__ float xs[64][68];
    __shared__ float Ws[64][68];

    const int b0 = blockIdx.y * 64;
    const int j0 = blockIdx.x * 64;
    const int tid = threadIdx.x;

    for (int i = tid; i < 64 * 64; i += 256) {
        int r = i >> 6, a = i & 63;
        float xv;
        if (s == 0) xv = (a == 0) ? 16.f : -16.f;
        else        xv = target[(size_t)(b0 + r) * (LL * AA) + (size_t)s * AA + a];
        xs[r][a] = xv;
        Ws[r][a] = W_ih[(size_t)(2 * HH + j0 + r) * AA + a];   // n-gate rows start at 1024
    }
    __syncthreads();

    const int tc = tid & 15;   // col group
    const int tr = tid >> 4;   // row group

    float inn[4][4];
#pragma unroll
    for (int i = 0; i < 4; i++)
#pragma unroll
        for (int j = 0; j < 4; j++) inn[i][j] = 0.f;

#pragma unroll
    for (int a4 = 0; a4 < 64; a4 += 4) {
        float4 xv[4], wv[4];
#pragma unroll
        for (int i = 0; i < 4; i++) xv[i] = *(const float4*)&xs[tr + 16 * i][a4];
#pragma unroll
        for (int j = 0; j < 4; j++) wv[j] = *(const float4*)&Ws[tc + 16 * j][a4];
#pragma unroll
        for (int i = 0; i < 4; i++)
#pragma unroll
            for (int j = 0; j < 4; j++)
                inn[i][j] += xv[i].x * wv[j].x + xv[i].y * wv[j].y
                           + xv[i].z * wv[j].z + xv[i].w * wv[j].w;
    }

#pragma unroll
    for (int i = 0; i < 4; i++) {
        int b = b0 + tr + 16 * i;
#pragma unroll
        for (int j = 0; j < 4; j++) {
            int jj = j0 + tc + 16 * j;
            const float* Ob = O + (size_t)b * NCAT;
            float rg = 1.f / (1.f + expf(-Ob[jj]));
            float zg = 1.f / (1.f + expf(-Ob[HH + jj]));
            float hn = Ob[2 * HH + jj];
            float n  = tanhf(inn[i][j] + b_ih[2 * HH + jj] + rg * hn);
            float hp = g_hx[(size_t)b * KCAT + jj];
            float hv = (1.f - zg) * n + zg * hp;
            hall_s[(size_t)b * HH + jj] = hv;
            g_hx[(size_t)b * KCAT + jj] = hv;
            // stage next x (only j-tile 0; j index == action index)
            if (j0 == 0 && s < NSTEP - 1) {
                g_hx[(size_t)b * KCAT + HH + jj] =
                    target[(size_t)b * (LL * AA) + (size_t)(s + 1) * AA + jj];
            }
        }
    }
}

// -------------------- prep: build concatenated recurrent weight --------------------
__global__ void prep_kernel(const float* __restrict__ W_hh, const float* __restrict__ W_ih,
                            const float* __restrict__ b_hh, const float* __restrict__ b_ih)
{
    int i = blockIdx.x * blockDim.x + threadIdx.x;
    if (i < NCAT * KCAT) {
        int j = i / KCAT, k = i % KCAT;
        float v;
        if (k < HH)            v = W_hh[(size_t)j * HH + k];
        else if (j < 2 * HH)   v = W_ih[(size_t)j * AA + (k - HH)];   // r,z gate x-weights
        else                   v = 0.f;                                // n gate handled in gates_kernel
        g_wcat[i] = v;
    }
    if (i < NCAT) g_bcat[i] = b_hh[i] + ((i < 2 * HH) ? b_ih[i] : 0.f);
}

// -------------------- BOS: out[:,0,:] and initial x staging --------------------
__global__ void bos_kernel(float* __restrict__ out)
{
    int i = blockIdx.x * blockDim.x + threadIdx.x;   // BB*AA threads
    if (i >= BB * AA) return;
    int b = i >> 6, a = i & 63;
    float v = (a == 0) ? 16.f : -16.f;
    out[(size_t)b * (LL * AA) + a] = v;
    g_hx[(size_t)b * KCAT + HH + a] = v;
}

// -------------------- launch --------------------
extern "C" void kernel_launch(void* const* d_in, const int* in_sizes, int n_in,
                              void* d_out, int out_size)
{
    const float* latent = (const float*)d_in[0];
    const float* target = (const float*)d_in[1];
    const float* Wd1 = (const float*)d_in[2];
    const float* bd1 = (const float*)d_in[3];
    const float* Wd2 = (const float*)d_in[4];
    const float* bd2 = (const float*)d_in[5];
    const float* Wd3 = (const float*)d_in[6];
    const float* bd3 = (const float*)d_in[7];
    const float* W_ih = (const float*)d_in[8];
    const float* W_hh = (const float*)d_in[9];
    const float* b_ih = (const float*)d_in[10];
    const float* b_hh = (const float*)d_in[11];
    const float* Wm1 = (const float*)d_in[12];
    const float* bm1 = (const float*)d_in[13];
    const float* Wm2 = (const float*)d_in[14];
    const float* bm2 = (const float*)d_in[15];
    const float* Wm3 = (const float*)d_in[16];
    const float* bm3 = (const float*)d_in[17];
    float* out = (float*)d_out;

    float *hx, *tmp1, *tmp2, *Obuf, *hall, *p1, *p2, *wcat, *bcat;
    cudaGetSymbolAddress((void**)&hx,   g_hx);
    cudaGetSymbolAddress((void**)&tmp1, g_tmp1);
    cudaGetSymbolAddress((void**)&tmp2, g_tmp2);
    cudaGetSymbolAddress((void**)&Obuf, g_O);
    cudaGetSymbolAddress((void**)&hall, g_hall);
    cudaGetSymbolAddress((void**)&p1,   g_p1);
    cudaGetSymbolAddress((void**)&p2,   g_p2);
    cudaGetSymbolAddress((void**)&wcat, g_wcat);
    cudaGetSymbolAddress((void**)&bcat, g_bcat);

    // prologue (parallel)
    prep_kernel<<<(NCAT * KCAT + 255) / 256, 256>>>(W_hh, W_ih, b_hh, b_ih);
    bos_kernel<<<(BB * AA + 255) / 256, 256>>>(out);

    // initial hidden: Linear(LAT,H)-tanh, Linear(H,H)-tanh, Linear(H,H)
    gemm_kernel<<<dim3(HH / GBN, BB / GBM), 256>>>(latent, LAT, Wd1, bd1, tmp1, HH, BB, HH, LAT, 1, 0);
    gemm_kernel<<<dim3(HH / GBN, BB / GBM), 256>>>(tmp1,  HH,  Wd2, bd2, tmp2, HH, BB, HH, HH,  1, 0);
    gemm_kernel<<<dim3(HH / GBN, BB / GBM), 256>>>(tmp2,  HH,  Wd3, bd3, hx, KCAT, BB, HH, HH,  0, 0);

    // sequential GRU core: 127 x (fused [h|x] GEMM + gate kernel)
    for (int s = 0; s < NSTEP; s++) {
        gemm_kernel<<<dim3(NCAT / GBN, BB / GBM), 256>>>(hx, KCAT, wcat, bcat, Obuf, NCAT,
                                                         BB, NCAT, KCAT, 0, 0);
        gates_kernel<<<dim3(HH / 64, BB / 64), 256>>>(Obuf, target, W_ih, b_ih,
                                                      hall + (size_t)s * BB * HH, s);
    }

    // deferred prediction head over all 127*4096 rows (parallel)
    const int M = NSTEP * BB;                 // 520192, % 128 == 0
    gemm_kernel<<<dim3(HH / GBN, M / GBM), 256>>>(hall, HH, Wm1, bm1, p1, HH, M, HH, HH, 1, 0);
    gemm_kernel<<<dim3(1,        M / GBM), 256>>>(p1,   HH, Wm2, bm2, p2, AA, M, AA, HH, 1, 0);
    gemm_kernel<<<dim3(1,        M / GBM), 256>>>(p2,   AA, Wm3, bm3, out, 0, M, AA, AA, 0, 1);
}

// round 6
// speedup vs baseline: 2.2598x; 2.2598x over previous
#include <cuda_runtime.h>
#include <cuda_bf16.h>
#include <cstddef>
#include <cstdint>

// Problem constants
#define BB    4096      // batch
#define LAT   256
#define HH    512
#define AA    64
#define LL    128
#define NSTEP 127       // L-1 sequential GRU steps
#define KCAT  576       // H + A
#define NCAT  1536      // 3H

typedef __nv_bfloat16 bf16;

// -------------------- scratch (__device__ globals, no allocs) --------------------
// activations as split bf16 planes (hi + lo)
__device__ __align__(256) bf16  g_lat_h[BB * LAT],  g_lat_l[BB * LAT];
__device__ __align__(256) bf16  g_hx_h [BB * KCAT], g_hx_l [BB * KCAT];   // [h | x]
__device__ __align__(256) bf16  g_t1_h [BB * HH],   g_t1_l [BB * HH];
__device__ __align__(256) bf16  g_t2_h [BB * HH],   g_t2_l [BB * HH];
__device__ __align__(256) float g_O    [BB * NCAT];                       // step GEMM out (fp32)
__device__ __align__(256) bf16  g_hall_h[(size_t)NSTEP * BB * HH];
__device__ __align__(256) bf16  g_hall_l[(size_t)NSTEP * BB * HH];
__device__ __align__(256) bf16  g_p1_h [(size_t)NSTEP * BB * HH];
__device__ __align__(256) bf16  g_p1_l [(size_t)NSTEP * BB * HH];
__device__ __align__(256) bf16  g_p2_h [(size_t)NSTEP * BB * AA];
__device__ __align__(256) bf16  g_p2_l [(size_t)NSTEP * BB * AA];
// weights as split bf16 planes
__device__ __align__(256) bf16  g_wc_h [NCAT * KCAT], g_wc_l [NCAT * KCAT];
__device__ __align__(256) bf16  g_wd1_h[HH * LAT],    g_wd1_l[HH * LAT];
__device__ __align__(256) bf16  g_wd2_h[HH * HH],     g_wd2_l[HH * HH];
__device__ __align__(256) bf16  g_wd3_h[HH * HH],     g_wd3_l[HH * HH];
__device__ __align__(256) bf16  g_wm1_h[HH * HH],     g_wm1_l[HH * HH];
__device__ __align__(256) bf16  g_wm2_h[AA * HH],     g_wm2_l[AA * HH];
__device__ __align__(256) bf16  g_wm3_h[AA * AA],     g_wm3_l[AA * AA];
__device__ __align__(256) float g_bcat[NCAT];

// -------------------- PTX helpers --------------------
__device__ __forceinline__ uint32_t smem_u32(const void* p) {
    return (uint32_t)__cvta_generic_to_shared(p);
}
__device__ __forceinline__ void cpasync16(uint32_t s, const void* g) {
    asm volatile("cp.async.cg.shared.global [%0], [%1], 16;\n" :: "r"(s), "l"(g));
}
__device__ __forceinline__ void ldmx4(uint32_t& r0, uint32_t& r1, uint32_t& r2, uint32_t& r3,
                                      uint32_t addr) {
    asm volatile("ldmatrix.sync.aligned.m8n8.x4.shared.b16 {%0,%1,%2,%3}, [%4];\n"
                 : "=r"(r0), "=r"(r1), "=r"(r2), "=r"(r3) : "r"(addr));
}
__device__ __forceinline__ void mma16816(float* c, const uint32_t* a, const uint32_t* b) {
    asm volatile(
        "mma.sync.aligned.m16n8k16.row.col.f32.bf16.bf16.f32 "
        "{%0,%1,%2,%3}, {%4,%5,%6,%7}, {%8,%9}, {%0,%1,%2,%3};\n"
        : "+f"(c[0]), "+f"(c[1]), "+f"(c[2]), "+f"(c[3])
        : "r"(a[0]), "r"(a[1]), "r"(a[2]), "r"(a[3]), "r"(b[0]), "r"(b[1]));
}
__device__ __forceinline__ void fsplit(float v, bf16& h, bf16& l) {
    h = __float2bfloat16(v);
    l = __float2bfloat16(v - __bfloat162float(h));
}
// 64B-row swizzle: chunk q = c ^ ((r>>1)&3) -> 8 consecutive rows hit 8 distinct bank groups
__device__ __forceinline__ uint32_t swz(int r, int c) {
    return (uint32_t)(r * 64 + ((c ^ ((r >> 1) & 3)) << 4));
}

// -------------------- split-bf16 tensor-core GEMM --------------------
// C[m,n] = act( sum_k A[m,k]*Bw[n,k] + bias[n] ), A=[M,K] row-major (contiguous),
// Bw=[N,K] row-major. A,B given as bf16 hi/lo planes; acc = Ah*Bh + Ah*Bl + Al*Bh.
// BM=128, BK=32, BN template (128 or 64). Requires M%128==0, N%BN==0, K%32==0.
// act: 0 none, 1 tanh. omode: 0 fp32 C (ldc), 1 split bf16 planes (ldc), 2 fp32 scatter to out.
template<int BN>
__global__ void __launch_bounds__(256)
mma_gemm(const bf16* __restrict__ Ahi, const bf16* __restrict__ Alo,
         const bf16* __restrict__ Bhi, const bf16* __restrict__ Blo,
         const float* __restrict__ bias,
         float* __restrict__ Cf, bf16* __restrict__ Chi, bf16* __restrict__ Clo,
         int M, int N, int K, int ldc, int act, int omode)
{
    constexpr int WN  = BN / 2;      // N per warp
    constexpr int NT  = WN / 8;      // n8-tiles per warp
    constexpr int NT2 = NT / 2;
    constexpr int A_BYTES = 128 * 64;
    constexpr int B_BYTES = BN * 64;
    constexpr int STAGE   = 2 * A_BYTES + 2 * B_BYTES;

    extern __shared__ char smem[];
    const uint32_t sbase = smem_u32(smem);
    const int tid = threadIdx.x;
    const int lane = tid & 31, wid = tid >> 5;
    const int wm = wid & 3, wn = wid >> 2;
    const int row0 = blockIdx.y * 128;
    const int col0 = blockIdx.x * BN;
    const int KT = K >> 5;

    float acc[2][NT][4];
#pragma unroll
    for (int t = 0; t < 2; t++)
#pragma unroll
        for (int n = 0; n < NT; n++)
#pragma unroll
            for (int i = 0; i < 4; i++) acc[t][n][i] = 0.f;

    auto load_stage = [&](int kt, int s) {
        const int k0 = kt << 5;
        const uint32_t so = sbase + s * STAGE;
#pragma unroll
        for (int i = 0; i < 2; i++) {                       // A: 128 rows x 4 chunks
            int l = tid + i * 256;
            int r = l >> 2, c = l & 3;
            uint32_t sa = so + swz(r, c);
            size_t go = (size_t)(row0 + r) * K + k0 + c * 8;
            cpasync16(sa,            Ahi + go);
            cpasync16(sa + A_BYTES,  Alo + go);
        }
#pragma unroll
        for (int i = 0; i < BN / 64; i++) {                 // B: BN rows x 4 chunks
            int l = tid + i * 256;
            int r = l >> 2, c = l & 3;
            uint32_t sb = so + 2 * A_BYTES + swz(r, c);
            size_t go = (size_t)(col0 + r) * K + k0 + c * 8;
            cpasync16(sb,            Bhi + go);
            cpasync16(sb + B_BYTES,  Blo + go);
        }
        asm volatile("cp.async.commit_group;\n" ::: "memory");
    };

    load_stage(0, 0);
    for (int kt = 0; kt < KT; kt++) {
        if (kt + 1 < KT) {
            load_stage(kt + 1, (kt + 1) & 1);
            asm volatile("cp.async.wait_group 1;\n" ::: "memory");
        } else {
            asm volatile("cp.async.wait_group 0;\n" ::: "memory");
        }
        __syncthreads();

        const uint32_t so = sbase + (kt & 1) * STAGE;
#pragma unroll
        for (int ks = 0; ks < 2; ks++) {
            uint32_t ah[2][4], al[2][4];
#pragma unroll
            for (int t = 0; t < 2; t++) {
                int r = wm * 32 + t * 16 + (lane & 7) + ((lane >> 3) & 1) * 8;
                int c = ks * 2 + (lane >> 4);
                uint32_t addr = so + swz(r, c);
                ldmx4(ah[t][0], ah[t][1], ah[t][2], ah[t][3], addr);
                ldmx4(al[t][0], al[t][1], al[t][2], al[t][3], addr + A_BYTES);
            }
#pragma unroll
            for (int p = 0; p < NT2; p++) {
                int r = wn * WN + p * 16 + (lane & 7) + (lane >> 4) * 8;
                int c = ks * 2 + ((lane >> 3) & 1);
                uint32_t addr = so + 2 * A_BYTES + swz(r, c);
                uint32_t bh[4], bl[4];
                ldmx4(bh[0], bh[1], bh[2], bh[3], addr);
                ldmx4(bl[0], bl[1], bl[2], bl[3], addr + B_BYTES);
#pragma unroll
                for (int t = 0; t < 2; t++) {
                    mma16816(acc[t][2 * p],     ah[t], bh);
                    mma16816(acc[t][2 * p],     ah[t], bl);
                    mma16816(acc[t][2 * p],     al[t], bh);
                    mma16816(acc[t][2 * p + 1], ah[t], bh + 2);
                    mma16816(acc[t][2 * p + 1], ah[t], bl + 2);
                    mma16816(acc[t][2 * p + 1], al[t], bh + 2);
                }
            }
        }
        __syncthreads();
    }

    // epilogue
#pragma unroll
    for (int t = 0; t < 2; t++) {
#pragma unroll
        for (int nt = 0; nt < NT; nt++) {
            int col = col0 + wn * WN + nt * 8 + (lane & 3) * 2;
            float b0 = bias[col], b1 = bias[col + 1];
#pragma unroll
            for (int h = 0; h < 2; h++) {
                int m = row0 + wm * 32 + t * 16 + (lane >> 2) + h * 8;
                float vx = acc[t][nt][2 * h + 0] + b0;
                float vy = acc[t][nt][2 * h + 1] + b1;
                if (act) { vx = tanhf(vx); vy = tanhf(vy); }
                if (omode == 0) {
                    size_t idx = (size_t)m * ldc + col;
                    Cf[idx] = vx; Cf[idx + 1] = vy;
                } else if (omode == 1) {
                    size_t idx = (size_t)m * ldc + col;
                    bf16 hx, lx; fsplit(vx, hx, lx);
                    bf16 hy, ly; fsplit(vy, hy, ly);
                    Chi[idx] = hx; Chi[idx + 1] = hy;
                    Clo[idx] = lx; Clo[idx + 1] = ly;
                } else {
                    int b = m & (BB - 1), s = m >> 12;
                    size_t idx = (size_t)b * (LL * AA) + (size_t)(s + 1) * AA + col;
                    Cf[idx] = vx; Cf[idx + 1] = vy;
                }
            }
        }
    }
}

// -------------------- GRU gate fusion kernel --------------------
__global__ void __launch_bounds__(256)
gates_kernel(const float* __restrict__ O,
             const float* __restrict__ target,   // [4096,128,64] fp32
             const float* __restrict__ W_ih,     // [1536,64] fp32
             const float* __restrict__ b_ih,
             bf16* __restrict__ hall_h, bf16* __restrict__ hall_l,  // + s*BB*HH
             int s)
{
    __shared__ float xs[64][68];
    __shared__ float Ws[64][68];

    const int b0 = blockIdx.y * 64;
    const int j0 = blockIdx.x * 64;
    const int tid = threadIdx.x;

    for (int i = tid; i < 64 * 64; i += 256) {
        int r = i >> 6, a = i & 63;
        float xv;
        if (s == 0) xv = (a == 0) ? 16.f : -16.f;
        else        xv = target[(size_t)(b0 + r) * (LL * AA) + (size_t)s * AA + a];
        xs[r][a] = xv;
        Ws[r][a] = W_ih[(size_t)(2 * HH + j0 + r) * AA + a];
    }
    __syncthreads();

    const int tc = tid & 15, tr = tid >> 4;

    float inn[4][4];
#pragma unroll
    for (int i = 0; i < 4; i++)
#pragma unroll
        for (int j = 0; j < 4; j++) inn[i][j] = 0.f;

#pragma unroll
    for (int a4 = 0; a4 < 64; a4 += 4) {
        float4 xv[4], wv[4];
#pragma unroll
        for (int i = 0; i < 4; i++) xv[i] = *(const float4*)&xs[tr + 16 * i][a4];
#pragma unroll
        for (int j = 0; j < 4; j++) wv[j] = *(const float4*)&Ws[tc + 16 * j][a4];
#pragma unroll
        for (int i = 0; i < 4; i++)
#pragma unroll
            for (int j = 0; j < 4; j++)
                inn[i][j] += xv[i].x * wv[j].x + xv[i].y * wv[j].y
                           + xv[i].z * wv[j].z + xv[i].w * wv[j].w;
    }

#pragma unroll
    for (int i = 0; i < 4; i++) {
        int b = b0 + tr + 16 * i;
#pragma unroll
        for (int j = 0; j < 4; j++) {
            int jj = j0 + tc + 16 * j;
            const float* Ob = O + (size_t)b * NCAT;
            float rg = 1.f / (1.f + expf(-Ob[jj]));
            float zg = 1.f / (1.f + expf(-Ob[HH + jj]));
            float hn = Ob[2 * HH + jj];
            float n  = tanhf(inn[i][j] + b_ih[2 * HH + jj] + rg * hn);
            size_t hxi = (size_t)b * KCAT + jj;
            float hp = __bfloat162float(g_hx_h[hxi]) + __bfloat162float(g_hx_l[hxi]);
            float hv = (1.f - zg) * n + zg * hp;
            bf16 hh, hl; fsplit(hv, hh, hl);
            hall_h[(size_t)b * HH + jj] = hh;
            hall_l[(size_t)b * HH + jj] = hl;
            g_hx_h[hxi] = hh;
            g_hx_l[hxi] = hl;
            if (j0 == 0 && s < NSTEP - 1) {
                float xv = target[(size_t)b * (LL * AA) + (size_t)(s + 1) * AA + jj];
                bf16 xh, xl; fsplit(xv, xh, xl);
                g_hx_h[(size_t)b * KCAT + HH + jj] = xh;
                g_hx_l[(size_t)b * KCAT + HH + jj] = xl;
            }
        }
    }
}

// -------------------- prep: concatenated recurrent weight -> split planes --------------------
__global__ void prep_kernel(const float* __restrict__ W_hh, const float* __restrict__ W_ih,
                            const float* __restrict__ b_hh, const float* __restrict__ b_ih)
{
    int i = blockIdx.x * blockDim.x + threadIdx.x;
    if (i < NCAT * KCAT) {
        int j = i / KCAT, k = i % KCAT;
        float v;
        if (k < HH)          v = W_hh[(size_t)j * HH + k];
        else if (j < 2 * HH) v = W_ih[(size_t)j * AA + (k - HH)];
        else                 v = 0.f;
        fsplit(v, g_wc_h[i], g_wc_l[i]);
    }
    if (i < NCAT) g_bcat[i] = b_hh[i] + ((i < 2 * HH) ? b_ih[i] : 0.f);
}

// -------------------- generic fp32 -> split bf16 --------------------
__global__ void split_kernel(const float* __restrict__ src, bf16* __restrict__ hi,
                             bf16* __restrict__ lo, int n)
{
    int i = blockIdx.x * blockDim.x + threadIdx.x;
    if (i < n) fsplit(src[i], hi[i], lo[i]);
}

// -------------------- BOS: out[:,0,:] + initial x staging --------------------
__global__ void bos_kernel(float* __restrict__ out)
{
    int i = blockIdx.x * blockDim.x + threadIdx.x;
    if (i >= BB * AA) return;
    int b = i >> 6, a = i & 63;
    float v = (a == 0) ? 16.f : -16.f;
    out[(size_t)b * (LL * AA) + a] = v;
    g_hx_h[(size_t)b * KCAT + HH + a] = __float2bfloat16(v);   // exact in bf16
    g_hx_l[(size_t)b * KCAT + HH + a] = __float2bfloat16(0.f);
}

// -------------------- launch --------------------
extern "C" void kernel_launch(void* const* d_in, const int* in_sizes, int n_in,
                              void* d_out, int out_size)
{
    const float* latent = (const float*)d_in[0];
    const float* target = (const float*)d_in[1];
    const float* Wd1 = (const float*)d_in[2];
    const float* bd1 = (const float*)d_in[3];
    const float* Wd2 = (const float*)d_in[4];
    const float* bd2 = (const float*)d_in[5];
    const float* Wd3 = (const float*)d_in[6];
    const float* bd3 = (const float*)d_in[7];
    const float* W_ih = (const float*)d_in[8];
    const float* W_hh = (const float*)d_in[9];
    const float* b_ih = (const float*)d_in[10];
    const float* b_hh = (const float*)d_in[11];
    const float* Wm1 = (const float*)d_in[12];
    const float* bm1 = (const float*)d_in[13];
    const float* Wm2 = (const float*)d_in[14];
    const float* bm2 = (const float*)d_in[15];
    const float* Wm3 = (const float*)d_in[16];
    const float* bm3 = (const float*)d_in[17];
    float* out = (float*)d_out;

    // resolve device-global addresses
    bf16 *lath, *latl, *hxh, *hxl, *t1h, *t1l, *t2h, *t2l;
    bf16 *hallh, *halll, *p1h, *p1l, *p2h, *p2l;
    bf16 *wch, *wcl, *wd1h, *wd1l, *wd2h, *wd2l, *wd3h, *wd3l;
    bf16 *wm1h, *wm1l, *wm2h, *wm2l, *wm3h, *wm3l;
    float *Obuf, *bcat;
    cudaGetSymbolAddress((void**)&lath, g_lat_h);  cudaGetSymbolAddress((void**)&latl, g_lat_l);
    cudaGetSymbolAddress((void**)&hxh,  g_hx_h);   cudaGetSymbolAddress((void**)&hxl,  g_hx_l);
    cudaGetSymbolAddress((void**)&t1h,  g_t1_h);   cudaGetSymbolAddress((void**)&t1l,  g_t1_l);
    cudaGetSymbolAddress((void**)&t2h,  g_t2_h);   cudaGetSymbolAddress((void**)&t2l,  g_t2_l);
    cudaGetSymbolAddress((void**)&hallh,g_hall_h); cudaGetSymbolAddress((void**)&halll,g_hall_l);
    cudaGetSymbolAddress((void**)&p1h,  g_p1_h);   cudaGetSymbolAddress((void**)&p1l,  g_p1_l);
    cudaGetSymbolAddress((void**)&p2h,  g_p2_h);   cudaGetSymbolAddress((void**)&p2l,  g_p2_l);
    cudaGetSymbolAddress((void**)&wch,  g_wc_h);   cudaGetSymbolAddress((void**)&wcl,  g_wc_l);
    cudaGetSymbolAddress((void**)&wd1h, g_wd1_h);  cudaGetSymbolAddress((void**)&wd1l, g_wd1_l);
    cudaGetSymbolAddress((void**)&wd2h, g_wd2_h);  cudaGetSymbolAddress((void**)&wd2l, g_wd2_l);
    cudaGetSymbolAddress((void**)&wd3h, g_wd3_h);  cudaGetSymbolAddress((void**)&wd3l, g_wd3_l);
    cudaGetSymbolAddress((void**)&wm1h, g_wm1_h);  cudaGetSymbolAddress((void**)&wm1l, g_wm1_l);
    cudaGetSymbolAddress((void**)&wm2h, g_wm2_h);  cudaGetSymbolAddress((void**)&wm2l, g_wm2_l);
    cudaGetSymbolAddress((void**)&wm3h, g_wm3_h);  cudaGetSymbolAddress((void**)&wm3l, g_wm3_l);
    cudaGetSymbolAddress((void**)&Obuf, g_O);
    cudaGetSymbolAddress((void**)&bcat, g_bcat);

    const int SM128 = 2 * (2 * 128 * 64 + 2 * 128 * 64);   // 65536
    const int SM64  = 2 * (2 * 128 * 64 + 2 *  64 * 64);   // 49152
    cudaFuncSetAttribute(mma_gemm<128>, cudaFuncAttributeMaxDynamicSharedMemorySize, SM128);
    cudaFuncSetAttribute(mma_gemm<64>,  cudaFuncAttributeMaxDynamicSharedMemorySize, SM64);

    // weight prep
    prep_kernel<<<(NCAT * KCAT + 255) / 256, 256>>>(W_hh, W_ih, b_hh, b_ih);
    split_kernel<<<(HH * LAT + 255) / 256, 256>>>(Wd1, wd1h, wd1l, HH * LAT);
    split_kernel<<<(HH * HH + 255) / 256, 256>>>(Wd2, wd2h, wd2l, HH * HH);
    split_kernel<<<(HH * HH + 255) / 256, 256>>>(Wd3, wd3h, wd3l, HH * HH);
    split_kernel<<<(HH * HH + 255) / 256, 256>>>(Wm1, wm1h, wm1l, HH * HH);
    split_kernel<<<(AA * HH + 255) / 256, 256>>>(Wm2, wm2h, wm2l, AA * HH);
    split_kernel<<<(AA * AA + 255) / 256, 256>>>(Wm3, wm3h, wm3l, AA * AA);
    split_kernel<<<(BB * LAT + 255) / 256, 256>>>(latent, lath, latl, BB * LAT);
    bos_kernel<<<(BB * AA + 255) / 256, 256>>>(out);

    // initial hidden: Linear(LAT,H)-tanh, Linear(H,H)-tanh, Linear(H,H) -> hx planes
    mma_gemm<128><<<dim3(HH / 128, BB / 128), 256, SM128>>>(
        lath, latl, wd1h, wd1l, bd1, nullptr, t1h, t1l, BB, HH, LAT, HH, 1, 1);
    mma_gemm<128><<<dim3(HH / 128, BB / 128), 256, SM128>>>(
        t1h, t1l, wd2h, wd2l, bd2, nullptr, t2h, t2l, BB, HH, HH, HH, 1, 1);
    mma_gemm<128><<<dim3(HH / 128, BB / 128), 256, SM128>>>(
        t2h, t2l, wd3h, wd3l, bd3, nullptr, hxh, hxl, BB, HH, HH, KCAT, 0, 1);

    // sequential GRU core
    for (int s = 0; s < NSTEP; s++) {
        mma_gemm<128><<<dim3(NCAT / 128, BB / 128), 256, SM128>>>(
            hxh, hxl, wch, wcl, bcat, Obuf, nullptr, nullptr, BB, NCAT, KCAT, NCAT, 0, 0);
        gates_kernel<<<dim3(HH / 64, BB / 64), 256>>>(
            Obuf, target, W_ih, b_ih,
            hallh + (size_t)s * BB * HH, halll + (size_t)s * BB * HH, s);
    }

    // deferred prediction head
    const int M = NSTEP * BB;   // 520192
    mma_gemm<128><<<dim3(HH / 128, M / 128), 256, SM128>>>(
        hallh, halll, wm1h, wm1l, bm1, nullptr, p1h, p1l, M, HH, HH, HH, 1, 1);
    mma_gemm<64><<<dim3(1, M / 128), 256, SM64>>>(
        p1h, p1l, wm2h, wm2l, bm2, nullptr, p2h, p2l, M, AA, HH, AA, 1, 1);
    mma_gemm<64><<<dim3(1, M / 128), 256, SM64>>>(
        p2h, p2l, wm3h, wm3l, bm3, out, nullptr, nullptr, M, AA, AA, 0, 0, 2);
}